// round 2
// baseline (speedup 1.0000x reference)
#include <cuda_runtime.h>
#include <math.h>

#define NB 4
#define NC 256
#define NT 4096   // tokens = H*W

// ---- scratch (static device memory; no allocs allowed) ----
__device__ float g_xn[NB * NT * NC];
__device__ float g_q [NB * NT * NC];
__device__ float g_k [NB * NT * NC];
__device__ float g_v [NB * NT * NC];
__device__ float g_s [(size_t)NB * NT * NT];   // 268 MB
__device__ float g_o [NB * NT * NC];

// ============================================================
// LayerNorm: x [B,C,N] (channel-major) -> xn [B,N,C] (token-major)
// One block = 32 tokens. Stage tile in smem for coalesced r/w.
// ============================================================
__global__ void __launch_bounds__(256) ln_kernel(
    const float* __restrict__ x, const float* __restrict__ gamma,
    const float* __restrict__ beta, float* __restrict__ xn)
{
    __shared__ float sx[32][NC + 1];     // [token][channel]
    __shared__ float psum[8][33];
    __shared__ float psq [8][33];
    __shared__ float smu[32], srs[32];

    int b  = blockIdx.y;
    int n0 = blockIdx.x * 32;
    const float* xb = x + (size_t)b * NC * NT;

    // coalesced load: consecutive threads -> consecutive tokens at fixed c
    for (int i = threadIdx.x; i < NC * 32; i += 256) {
        int c = i >> 5, t = i & 31;
        sx[t][c] = xb[(size_t)c * NT + n0 + t];
    }
    __syncthreads();

    int t = threadIdx.x & 31, g = threadIdx.x >> 5;
    float s0 = 0.f, s1 = 0.f;
#pragma unroll
    for (int j = 0; j < 32; j++) {
        float vv = sx[t][g * 32 + j];
        s0 += vv; s1 += vv * vv;
    }
    psum[g][t] = s0; psq[g][t] = s1;
    __syncthreads();

    if (threadIdx.x < 32) {
        float a = 0.f, bb = 0.f;
#pragma unroll
        for (int j = 0; j < 8; j++) { a += psum[j][threadIdx.x]; bb += psq[j][threadIdx.x]; }
        float mu  = a * (1.0f / NC);
        float var = bb * (1.0f / NC) - mu * mu;
        smu[threadIdx.x] = mu;
        srs[threadIdx.x] = rsqrtf(var + 1e-5f);
    }
    __syncthreads();

    float* xnb = xn + ((size_t)b * NT + n0) * NC;
    for (int i = threadIdx.x; i < NC * 32; i += 256) {
        int tok = i >> 8, c = i & 255;
        xnb[(size_t)tok * NC + c] = (sx[tok][c] - smu[tok]) * srs[tok] * gamma[c] + beta[c];
    }
}

// ============================================================
// SGEMM: C[MxN] = A[MxK] * B  (B is KxN if !TRANSB, NxK if TRANSB)
// 128x128 tile, BK=8, 256 threads, 8x8 per thread.
// blockIdx.z = batch (strides sA/sB/sC in elements).
// All dims are multiples of the tile sizes -> no bounds checks.
// ============================================================
template <bool TRANSB>
__global__ void __launch_bounds__(256) sgemm_kernel(
    const float* __restrict__ A, const float* __restrict__ Bm, float* __restrict__ Cm,
    int M, int N, int K, size_t sA, size_t sB, size_t sC)
{
    constexpr int BM = 128, BN = 128, BK = 8;
    __shared__ float As[BK][BM];
    __shared__ float Bs[BK][BN];

    A  += (size_t)blockIdx.z * sA + (size_t)blockIdx.y * BM * K;
    if (TRANSB) Bm += (size_t)blockIdx.z * sB + (size_t)blockIdx.x * BN * K;
    else        Bm += (size_t)blockIdx.z * sB + (size_t)blockIdx.x * BN;
    Cm += (size_t)blockIdx.z * sC + (size_t)blockIdx.y * BM * N + (size_t)blockIdx.x * BN;

    int tid  = threadIdx.x;
    int aRow = tid >> 1;            // 0..127
    int aCol = (tid & 1) * 4;       // 0 or 4
    int bRowN = tid >> 5;           // 0..7   (NN load)
    int bColN = (tid & 31) * 4;     // 0..124 (NN load)

    float acc[8][8] = {};

    for (int kk = 0; kk < K; kk += BK) {
        float4 av = *(const float4*)(A + (size_t)aRow * K + kk + aCol);
        As[aCol + 0][aRow] = av.x; As[aCol + 1][aRow] = av.y;
        As[aCol + 2][aRow] = av.z; As[aCol + 3][aRow] = av.w;

        if (TRANSB) {
            float4 bv = *(const float4*)(Bm + (size_t)aRow * K + kk + aCol);
            Bs[aCol + 0][aRow] = bv.x; Bs[aCol + 1][aRow] = bv.y;
            Bs[aCol + 2][aRow] = bv.z; Bs[aCol + 3][aRow] = bv.w;
        } else {
            *(float4*)(&Bs[bRowN][bColN]) =
                *(const float4*)(Bm + (size_t)(kk + bRowN) * N + bColN);
        }
        __syncthreads();

        int tr = (tid >> 4) * 8, tc = (tid & 15) * 8;
#pragma unroll
        for (int k = 0; k < BK; k++) {
            float4 m0 = *(const float4*)&As[k][tr];
            float4 m1 = *(const float4*)&As[k][tr + 4];
            float4 q0 = *(const float4*)&Bs[k][tc];
            float4 q1 = *(const float4*)&Bs[k][tc + 4];
            float rm[8] = {m0.x, m0.y, m0.z, m0.w, m1.x, m1.y, m1.z, m1.w};
            float rn[8] = {q0.x, q0.y, q0.z, q0.w, q1.x, q1.y, q1.z, q1.w};
#pragma unroll
            for (int i = 0; i < 8; i++)
#pragma unroll
                for (int j = 0; j < 8; j++)
                    acc[i][j] += rm[i] * rn[j];
        }
        __syncthreads();
    }

    int tr = (tid >> 4) * 8, tc = (tid & 15) * 8;
#pragma unroll
    for (int i = 0; i < 8; i++) {
        float4 v0 = make_float4(acc[i][0], acc[i][1], acc[i][2], acc[i][3]);
        float4 v1 = make_float4(acc[i][4], acc[i][5], acc[i][6], acc[i][7]);
        *(float4*)(Cm + (size_t)(tr + i) * N + tc)     = v0;
        *(float4*)(Cm + (size_t)(tr + i) * N + tc + 4) = v1;
    }
}

// ============================================================
// Row-wise mix: S[n,:] -> a1*softmax + a2*relu(S)^2, in place.
// One block per row (4096 elems, 256 threads x 16).
// ============================================================
__global__ void __launch_bounds__(256) mix_kernel(
    const float* __restrict__ w1, const float* __restrict__ w2, float* __restrict__ S)
{
    float* row = S + ((size_t)blockIdx.y * NT + blockIdx.x) * NT;
    int tid = threadIdx.x;
    __shared__ float sred[8];

    float v[16];
    float mx = -1e30f;
#pragma unroll
    for (int i = 0; i < 16; i++) { v[i] = row[i * 256 + tid]; mx = fmaxf(mx, v[i]); }

#pragma unroll
    for (int o = 16; o; o >>= 1) mx = fmaxf(mx, __shfl_xor_sync(0xffffffffu, mx, o));
    if ((tid & 31) == 0) sred[tid >> 5] = mx;
    __syncthreads();
    mx = sred[0];
#pragma unroll
    for (int i = 1; i < 8; i++) mx = fmaxf(mx, sred[i]);
    __syncthreads();

    float e[16]; float sum = 0.f;
#pragma unroll
    for (int i = 0; i < 16; i++) { e[i] = __expf(v[i] - mx); sum += e[i]; }
#pragma unroll
    for (int o = 16; o; o >>= 1) sum += __shfl_xor_sync(0xffffffffu, sum, o);
    if ((tid & 31) == 0) sred[tid >> 5] = sum;
    __syncthreads();
    sum = 0.f;
#pragma unroll
    for (int i = 0; i < 8; i++) sum += sred[i];

    float e1 = __expf(w1[0]), e2 = __expf(w2[0]);
    float a1 = e1 / (e1 + e2), a2 = e2 / (e1 + e2);
    float inv = a1 / sum;
#pragma unroll
    for (int i = 0; i < 16; i++) {
        float r = fmaxf(v[i], 0.0f);
        row[i * 256 + tid] = e[i] * inv + a2 * r * r;
    }
}

// ============================================================
// out[b,c,n] = o_bnc[b,n,c] + xn[b,n,c]   (transpose + residual)
// ============================================================
__global__ void out_kernel(const float* __restrict__ o, const float* __restrict__ xn,
                           float* __restrict__ out)
{
    __shared__ float tile[32][33];
    int b = blockIdx.z;
    int n0 = blockIdx.x * 32, c0 = blockIdx.y * 32;

    for (int r = threadIdx.y; r < 32; r += 8) {
        size_t idx = ((size_t)b * NT + n0 + r) * NC + c0 + threadIdx.x;
        tile[r][threadIdx.x] = o[idx] + xn[idx];
    }
    __syncthreads();
    for (int r = threadIdx.y; r < 32; r += 8) {
        out[((size_t)b * NC + c0 + r) * NT + n0 + threadIdx.x] = tile[threadIdx.x][r];
    }
}

// ============================================================
extern "C" void kernel_launch(void* const* d_in, const int* in_sizes, int n_in,
                              void* d_out, int out_size)
{
    const float* x     = (const float*)d_in[0];
    const float* gamma = (const float*)d_in[1];
    const float* beta  = (const float*)d_in[2];
    const float* Wq    = (const float*)d_in[3];
    const float* Wk    = (const float*)d_in[4];
    const float* Wv    = (const float*)d_in[5];
    const float* w1    = (const float*)d_in[6];
    const float* w2    = (const float*)d_in[7];
    float* out = (float*)d_out;

    float *xn, *q, *k, *v, *s, *o;
    cudaGetSymbolAddress((void**)&xn, g_xn);
    cudaGetSymbolAddress((void**)&q,  g_q);
    cudaGetSymbolAddress((void**)&k,  g_k);
    cudaGetSymbolAddress((void**)&v,  g_v);
    cudaGetSymbolAddress((void**)&s,  g_s);
    cudaGetSymbolAddress((void**)&o,  g_o);

    // 1) LayerNorm + layout change to [B,N,C]
    ln_kernel<<<dim3(NT / 32, NB), 256>>>(x, gamma, beta, xn);

    // 2) Q/K/V projections: [B*N, C] @ [C, C]
    sgemm_kernel<false><<<dim3(NC / 128, (NB * NT) / 128, 1), 256>>>(
        xn, Wq, q, NB * NT, NC, NC, 0, 0, 0);
    sgemm_kernel<false><<<dim3(NC / 128, (NB * NT) / 128, 1), 256>>>(
        xn, Wk, k, NB * NT, NC, NC, 0, 0, 0);
    sgemm_kernel<false><<<dim3(NC / 128, (NB * NT) / 128, 1), 256>>>(
        xn, Wv, v, NB * NT, NC, NC, 0, 0, 0);

    // 3) S = Q @ K^T per batch  [4096 x 4096 x 256]
    sgemm_kernel<true><<<dim3(NT / 128, NT / 128, NB), 256>>>(
        q, k, s, NT, NT, NC,
        (size_t)NT * NC, (size_t)NT * NC, (size_t)NT * NT);

    // 4) attn = a1*softmax(S) + a2*relu(S)^2  (row-wise, in place)
    mix_kernel<<<dim3(NT, NB), 256>>>(w1, w2, s);

    // 5) O = attn @ V per batch  [4096 x 256 x 4096]
    sgemm_kernel<false><<<dim3(NC / 128, NT / 128, NB), 256>>>(
        s, v, o, NT, NC, NT,
        (size_t)NT * NT, (size_t)NT * NC, (size_t)NT * NC);

    // 6) transpose back to [B,C,H,W] + residual xn
    out_kernel<<<dim3(NT / 32, NC / 32, NB), dim3(32, 8)>>>(o, xn, out);
}

// round 4
// speedup vs baseline: 2.8340x; 2.8340x over previous
#include <cuda_runtime.h>
#include <cuda_bf16.h>
#include <math.h>
#include <stdint.h>

#define NB 4
#define NC 256
#define NT 4096   // tokens = H*W

// ---------------- scratch (static device memory) ----------------
__device__ __nv_bfloat16 g_xnhi[NB * NT * NC];
__device__ __nv_bfloat16 g_xnlo[NB * NT * NC];
__device__ __nv_bfloat16 g_qhi [NB * NT * NC];
__device__ __nv_bfloat16 g_qlo [NB * NT * NC];
__device__ __nv_bfloat16 g_khi [NB * NT * NC];
__device__ __nv_bfloat16 g_klo [NB * NT * NC];
__device__ __nv_bfloat16 g_vThi[NC * NB * NT];   // [C, B*NT]
__device__ __nv_bfloat16 g_vTlo[NC * NB * NT];
__device__ float         g_s   [(size_t)NB * NT * NT];
__device__ __nv_bfloat16 g_ahi [(size_t)NB * NT * NT];
__device__ __nv_bfloat16 g_alo [(size_t)NB * NT * NT];
__device__ float         g_o   [NB * NT * NC];
__device__ __nv_bfloat16 g_wqhi[NC * NC], g_wqlo[NC * NC];
__device__ __nv_bfloat16 g_wkhi[NC * NC], g_wklo[NC * NC];
__device__ __nv_bfloat16 g_wvhi[NC * NC], g_wvlo[NC * NC];

// ---------------- PTX helpers (all legal on compute_103) ----------------
__device__ __forceinline__ uint32_t smem_u32(const void* p) {
    uint32_t a;
    asm("{ .reg .u64 t; cvta.to.shared.u64 t, %1; cvt.u32.u64 %0, t; }"
        : "=r"(a) : "l"(p));
    return a;
}
__device__ __forceinline__ void cp16(uint32_t s, const void* g) {
    asm volatile("cp.async.cg.shared.global [%0], [%1], 16;" :: "r"(s), "l"(g));
}
__device__ __forceinline__ void cp_commit() {
    asm volatile("cp.async.commit_group;" ::: "memory");
}
template <int N> __device__ __forceinline__ void cp_wait() {
    asm volatile("cp.async.wait_group %0;" :: "n"(N) : "memory");
}
__device__ __forceinline__ void ldm_x4(uint32_t* r, uint32_t addr) {
    asm volatile("ldmatrix.sync.aligned.m8n8.x4.shared.b16 {%0,%1,%2,%3}, [%4];"
                 : "=r"(r[0]), "=r"(r[1]), "=r"(r[2]), "=r"(r[3]) : "r"(addr));
}
__device__ __forceinline__ void mma16816(float* d, const uint32_t* a, const uint32_t* b) {
    asm volatile(
        "mma.sync.aligned.m16n8k16.row.col.f32.bf16.bf16.f32 "
        "{%0,%1,%2,%3}, {%4,%5,%6,%7}, {%8,%9}, {%0,%1,%2,%3};"
        : "+f"(d[0]), "+f"(d[1]), "+f"(d[2]), "+f"(d[3])
        : "r"(a[0]), "r"(a[1]), "r"(a[2]), "r"(a[3]), "r"(b[0]), "r"(b[1]));
}
__device__ __forceinline__ uint32_t swz(uint32_t off) {     // SW128
    return off ^ ((off >> 3) & 0x70);
}

// ============================================================
// split-bf16 GEMM via mma.sync:
//   D[M,N] = Ahi*Bhi^T + Ahi*Blo^T + Alo*Bhi^T
// A: [M,K] K-major (ld ldA), B: [N,K] K-major (ld ldB).
// BM=BN=128, BK=32. 256 thr = 8 warps (2 x 4), warp tile 64x32.
// smem row = 128B: [hi 32 bf16 | lo 32 bf16], SW128 swizzle.
// EPI=0: fp32 out. EPI=1: bf16 hi/lo split pair out.
// ============================================================
template <int EPI>
__global__ void __launch_bounds__(256) mma_gemm(
    const __nv_bfloat16* __restrict__ Ahi, const __nv_bfloat16* __restrict__ Alo,
    long ldA, long strideA,
    const __nv_bfloat16* __restrict__ Bhi, const __nv_bfloat16* __restrict__ Blo,
    long ldB, long strideB,
    float* __restrict__ Cf, __nv_bfloat16* __restrict__ Chi, __nv_bfloat16* __restrict__ Clo,
    long ldC, long strideC, int K)
{
    extern __shared__ char dyn_smem[];
    const uint32_t sbase = smem_u32(dyn_smem);
    const int tid  = threadIdx.x;
    const int wid  = tid >> 5, lane = tid & 31;
    const int warpM = wid & 1;          // 0..1 -> 64-row halves
    const int warpN = wid >> 1;         // 0..3 -> 32-col quarters

    const int z = blockIdx.z;
    const long m0 = (long)blockIdx.y * 128;
    const long n0 = (long)blockIdx.x * 128;
    const __nv_bfloat16* pAh = Ahi + (size_t)z * strideA + (size_t)m0 * ldA;
    const __nv_bfloat16* pAl = Alo + (size_t)z * strideA + (size_t)m0 * ldA;
    const __nv_bfloat16* pBh = Bhi + (size_t)z * strideB + (size_t)n0 * ldB;
    const __nv_bfloat16* pBl = Blo + (size_t)z * strideB + (size_t)n0 * ldB;

    const int nk = K / 32;
    const uint32_t STAGE = 32768;       // A 16KB + B 16KB

    // stage loader: A tile rows 0..127, B tile rows 0..127, 8 chunks of 16B/row
    auto load_stage = [&](int st, int ks) {
        uint32_t base = sbase + st * STAGE;
#pragma unroll
        for (int i = 0; i < 4; i++) {
            int cid = tid + i * 256;          // 0..1023
            int m = cid >> 3, c = cid & 7;    // row, chunk
            int part = c >> 2, kc = c & 3;    // hi/lo, 8-elem k-chunk
            uint32_t off = swz((uint32_t)(m * 128 + c * 16));
            const __nv_bfloat16* ga = (part ? pAl : pAh) + (size_t)m * ldA + ks * 32 + kc * 8;
            const __nv_bfloat16* gb = (part ? pBl : pBh) + (size_t)m * ldB + ks * 32 + kc * 8;
            cp16(base + off, ga);
            cp16(base + 16384u + off, gb);
        }
    };

    float acc[4][4][4] = {};   // [mf][nf][frag]

    load_stage(0, 0);
    cp_commit();

    const int lr = lane & 7, lg = lane >> 3;   // ldmatrix row / group

    for (int ks = 0; ks < nk; ks++) {
        int cur = ks & 1;
        if (ks + 1 < nk) {
            load_stage(cur ^ 1, ks + 1);
            cp_commit();
            cp_wait<1>();
        } else {
            cp_wait<0>();
        }
        __syncthreads();

        uint32_t aBase = sbase + cur * STAGE;
        uint32_t bBase = aBase + 16384u;

#pragma unroll
        for (int kst = 0; kst < 2; kst++) {
            const uint32_t kb = kst * 32;      // byte offset of k16 step within hi half

            // ---- A hi fragments (4 x m16) ----
            uint32_t ah[4][4];
#pragma unroll
            for (int mf = 0; mf < 4; mf++) {
                uint32_t row = warpM * 64 + mf * 16 + lr + ((lg & 1) << 3);
                uint32_t off = row * 128 + kb + ((lg >> 1) << 4);
                ldm_x4(ah[mf], aBase + swz(off));
            }
            // ---- B hi fragments (4 x n8) ----
            uint32_t bh[4][2];
#pragma unroll
            for (int p = 0; p < 2; p++) {
                uint32_t row = warpN * 32 + p * 16 + lr + ((lg >> 1) << 3);
                uint32_t off = row * 128 + kb + ((lg & 1) << 4);
                uint32_t t[4];
                ldm_x4(t, bBase + swz(off));
                bh[2*p][0] = t[0]; bh[2*p][1] = t[1];
                bh[2*p+1][0] = t[2]; bh[2*p+1][1] = t[3];
            }
            // hi * hi
#pragma unroll
            for (int mf = 0; mf < 4; mf++)
#pragma unroll
                for (int nf = 0; nf < 4; nf++)
                    mma16816(acc[mf][nf], ah[mf], bh[nf]);

            // ---- B lo fragments, hi * lo ----
            uint32_t bl[4][2];
#pragma unroll
            for (int p = 0; p < 2; p++) {
                uint32_t row = warpN * 32 + p * 16 + lr + ((lg >> 1) << 3);
                uint32_t off = row * 128 + 64 + kb + ((lg & 1) << 4);
                uint32_t t[4];
                ldm_x4(t, bBase + swz(off));
                bl[2*p][0] = t[0]; bl[2*p][1] = t[1];
                bl[2*p+1][0] = t[2]; bl[2*p+1][1] = t[3];
            }
#pragma unroll
            for (int mf = 0; mf < 4; mf++)
#pragma unroll
                for (int nf = 0; nf < 4; nf++)
                    mma16816(acc[mf][nf], ah[mf], bl[nf]);

            // ---- A lo fragments, lo * hi ----
#pragma unroll
            for (int mf = 0; mf < 4; mf++) {
                uint32_t al[4];
                uint32_t row = warpM * 64 + mf * 16 + lr + ((lg & 1) << 3);
                uint32_t off = row * 128 + 64 + kb + ((lg >> 1) << 4);
                ldm_x4(al, aBase + swz(off));
#pragma unroll
                for (int nf = 0; nf < 4; nf++)
                    mma16816(acc[mf][nf], al, bh[nf]);
            }
        }
        __syncthreads();
    }

    // -------- epilogue --------
    const int qr = lane >> 2;          // 0..7
    const int qc = (lane & 3) * 2;     // 0,2,4,6
#pragma unroll
    for (int mf = 0; mf < 4; mf++) {
#pragma unroll
        for (int nf = 0; nf < 4; nf++) {
            long r0  = m0 + warpM * 64 + mf * 16 + qr;
            long col = n0 + warpN * 32 + nf * 8 + qc;
            if (EPI == 0) {
                float* d0 = Cf + (size_t)z * strideC + (size_t)r0 * ldC + col;
                *(float2*)d0                          = make_float2(acc[mf][nf][0], acc[mf][nf][1]);
                *(float2*)(d0 + 8 * ldC)              = make_float2(acc[mf][nf][2], acc[mf][nf][3]);
            } else {
#pragma unroll
                for (int h = 0; h < 2; h++) {
                    float v0 = acc[mf][nf][2*h], v1 = acc[mf][nf][2*h+1];
                    __nv_bfloat16 h0 = __float2bfloat16(v0);
                    __nv_bfloat16 h1 = __float2bfloat16(v1);
                    __nv_bfloat16 l0 = __float2bfloat16(v0 - __bfloat162float(h0));
                    __nv_bfloat16 l1 = __float2bfloat16(v1 - __bfloat162float(h1));
                    size_t idx = (size_t)z * strideC + (size_t)(r0 + h * 8) * ldC + col;
                    *(uint32_t*)(Chi + idx) =
                        (uint32_t)__bfloat16_as_ushort(h0) | ((uint32_t)__bfloat16_as_ushort(h1) << 16);
                    *(uint32_t*)(Clo + idx) =
                        (uint32_t)__bfloat16_as_ushort(l0) | ((uint32_t)__bfloat16_as_ushort(l1) << 16);
                }
            }
        }
    }
}

// ============================================================
// LayerNorm: x [B,C,N] -> xn split bf16 [B,N,C]
// ============================================================
__global__ void __launch_bounds__(256) ln_kernel(
    const float* __restrict__ x, const float* __restrict__ gamma,
    const float* __restrict__ beta,
    __nv_bfloat16* __restrict__ xnhi, __nv_bfloat16* __restrict__ xnlo)
{
    __shared__ float sx[32][NC + 1];
    __shared__ float psum[8][33];
    __shared__ float psq [8][33];
    __shared__ float smu[32], srs[32];

    int b  = blockIdx.y;
    int n0 = blockIdx.x * 32;
    const float* xb = x + (size_t)b * NC * NT;

    for (int i = threadIdx.x; i < NC * 32; i += 256) {
        int c = i >> 5, t = i & 31;
        sx[t][c] = xb[(size_t)c * NT + n0 + t];
    }
    __syncthreads();

    int t = threadIdx.x & 31, g = threadIdx.x >> 5;
    float s0 = 0.f, s1 = 0.f;
#pragma unroll
    for (int j = 0; j < 32; j++) {
        float vv = sx[t][g * 32 + j];
        s0 += vv; s1 += vv * vv;
    }
    psum[g][t] = s0; psq[g][t] = s1;
    __syncthreads();

    if (threadIdx.x < 32) {
        float a = 0.f, bb = 0.f;
#pragma unroll
        for (int j = 0; j < 8; j++) { a += psum[j][threadIdx.x]; bb += psq[j][threadIdx.x]; }
        float mu  = a * (1.0f / NC);
        float var = bb * (1.0f / NC) - mu * mu;
        smu[threadIdx.x] = mu;
        srs[threadIdx.x] = rsqrtf(var + 1e-5f);
    }
    __syncthreads();

    size_t base = ((size_t)b * NT + n0) * NC;
    for (int i = threadIdx.x; i < NC * 32; i += 256) {
        int tok = i >> 8, c = i & 255;
        float r = (sx[tok][c] - smu[tok]) * srs[tok] * gamma[c] + beta[c];
        __nv_bfloat16 h = __float2bfloat16(r);
        xnhi[base + (size_t)tok * NC + c] = h;
        xnlo[base + (size_t)tok * NC + c] = __float2bfloat16(r - __bfloat162float(h));
    }
}

// ============================================================
// Weight transpose + split: out[n,k] = split(W[k,n])
// ============================================================
__global__ void wsplitT_kernel(const float* __restrict__ W,
                               __nv_bfloat16* __restrict__ hiT, __nv_bfloat16* __restrict__ loT)
{
    int n = blockIdx.x, k = threadIdx.x;
    float v = W[(size_t)k * NC + n];
    __nv_bfloat16 h = __float2bfloat16(v);
    hiT[(size_t)n * NC + k] = h;
    loT[(size_t)n * NC + k] = __float2bfloat16(v - __bfloat162float(h));
}

// ============================================================
// mix: S row -> a1*softmax + a2*relu^2, split bf16 out
// ============================================================
__global__ void __launch_bounds__(256) mix_kernel(
    const float* __restrict__ w1, const float* __restrict__ w2,
    const float* __restrict__ S,
    __nv_bfloat16* __restrict__ ahi, __nv_bfloat16* __restrict__ alo)
{
    size_t ro = ((size_t)blockIdx.y * NT + blockIdx.x) * NT;
    const float4* row4 = (const float4*)(S + ro);
    int tid = threadIdx.x;
    __shared__ float sred[8];

    float4 v[4];
    float mx = -1e30f;
#pragma unroll
    for (int g = 0; g < 4; g++) {
        v[g] = row4[g * 256 + tid];
        mx = fmaxf(mx, fmaxf(fmaxf(v[g].x, v[g].y), fmaxf(v[g].z, v[g].w)));
    }
#pragma unroll
    for (int o = 16; o; o >>= 1) mx = fmaxf(mx, __shfl_xor_sync(0xffffffffu, mx, o));
    if ((tid & 31) == 0) sred[tid >> 5] = mx;
    __syncthreads();
    mx = sred[0];
#pragma unroll
    for (int i = 1; i < 8; i++) mx = fmaxf(mx, sred[i]);
    __syncthreads();

    float4 e[4];
    float sum = 0.f;
#pragma unroll
    for (int g = 0; g < 4; g++) {
        e[g].x = __expf(v[g].x - mx); e[g].y = __expf(v[g].y - mx);
        e[g].z = __expf(v[g].z - mx); e[g].w = __expf(v[g].w - mx);
        sum += e[g].x + e[g].y + e[g].z + e[g].w;
    }
#pragma unroll
    for (int o = 16; o; o >>= 1) sum += __shfl_xor_sync(0xffffffffu, sum, o);
    if ((tid & 31) == 0) sred[tid >> 5] = sum;
    __syncthreads();
    sum = 0.f;
#pragma unroll
    for (int i = 0; i < 8; i++) sum += sred[i];

    float e1 = __expf(w1[0]), e2 = __expf(w2[0]);
    float a1 = e1 / (e1 + e2), a2 = e2 / (e1 + e2);
    float inv = a1 / sum;

    uint2* oh = (uint2*)(ahi + ro);
    uint2* ol = (uint2*)(alo + ro);
#pragma unroll
    for (int g = 0; g < 4; g++) {
        float o4[4] = {
            e[g].x * inv + a2 * fmaxf(v[g].x, 0.f) * fmaxf(v[g].x, 0.f),
            e[g].y * inv + a2 * fmaxf(v[g].y, 0.f) * fmaxf(v[g].y, 0.f),
            e[g].z * inv + a2 * fmaxf(v[g].z, 0.f) * fmaxf(v[g].z, 0.f),
            e[g].w * inv + a2 * fmaxf(v[g].w, 0.f) * fmaxf(v[g].w, 0.f)
        };
        unsigned short hb[4], lb[4];
#pragma unroll
        for (int j = 0; j < 4; j++) {
            __nv_bfloat16 h = __float2bfloat16(o4[j]);
            hb[j] = __bfloat16_as_ushort(h);
            lb[j] = __bfloat16_as_ushort(__float2bfloat16(o4[j] - __bfloat162float(h)));
        }
        oh[g * 256 + tid] = make_uint2((uint32_t)hb[0] | ((uint32_t)hb[1] << 16),
                                       (uint32_t)hb[2] | ((uint32_t)hb[3] << 16));
        ol[g * 256 + tid] = make_uint2((uint32_t)lb[0] | ((uint32_t)lb[1] << 16),
                                       (uint32_t)lb[2] | ((uint32_t)lb[3] << 16));
    }
}

// ============================================================
// out[b,c,n] = o[b,n,c] + (xnhi+xnlo)[b,n,c]
// ============================================================
__global__ void out_kernel(const float* __restrict__ o,
                           const __nv_bfloat16* __restrict__ xnhi,
                           const __nv_bfloat16* __restrict__ xnlo,
                           float* __restrict__ out)
{
    __shared__ float tile[32][33];
    int b = blockIdx.z;
    int n0 = blockIdx.x * 32, c0 = blockIdx.y * 32;

    for (int r = threadIdx.y; r < 32; r += 8) {
        size_t idx = ((size_t)b * NT + n0 + r) * NC + c0 + threadIdx.x;
        tile[r][threadIdx.x] = o[idx] + __bfloat162float(xnhi[idx]) + __bfloat162float(xnlo[idx]);
    }
    __syncthreads();
    for (int r = threadIdx.y; r < 32; r += 8) {
        out[((size_t)b * NC + c0 + r) * NT + n0 + threadIdx.x] = tile[threadIdx.x][r];
    }
}

// ============================================================
extern "C" void kernel_launch(void* const* d_in, const int* in_sizes, int n_in,
                              void* d_out, int out_size)
{
    const float* x     = (const float*)d_in[0];
    const float* gamma = (const float*)d_in[1];
    const float* beta  = (const float*)d_in[2];
    const float* Wq    = (const float*)d_in[3];
    const float* Wk    = (const float*)d_in[4];
    const float* Wv    = (const float*)d_in[5];
    const float* w1    = (const float*)d_in[6];
    const float* w2    = (const float*)d_in[7];
    float* out = (float*)d_out;

    __nv_bfloat16 *xnhi, *xnlo, *qhi, *qlo, *khi, *klo, *vThi, *vTlo;
    __nv_bfloat16 *wqhi, *wqlo, *wkhi, *wklo, *wvhi, *wvlo, *ahi, *alo;
    float *s, *o;
    cudaGetSymbolAddress((void**)&xnhi, g_xnhi); cudaGetSymbolAddress((void**)&xnlo, g_xnlo);
    cudaGetSymbolAddress((void**)&qhi,  g_qhi);  cudaGetSymbolAddress((void**)&qlo,  g_qlo);
    cudaGetSymbolAddress((void**)&khi,  g_khi);  cudaGetSymbolAddress((void**)&klo,  g_klo);
    cudaGetSymbolAddress((void**)&vThi, g_vThi); cudaGetSymbolAddress((void**)&vTlo, g_vTlo);
    cudaGetSymbolAddress((void**)&wqhi, g_wqhi); cudaGetSymbolAddress((void**)&wqlo, g_wqlo);
    cudaGetSymbolAddress((void**)&wkhi, g_wkhi); cudaGetSymbolAddress((void**)&wklo, g_wklo);
    cudaGetSymbolAddress((void**)&wvhi, g_wvhi); cudaGetSymbolAddress((void**)&wvlo, g_wvlo);
    cudaGetSymbolAddress((void**)&ahi,  g_ahi);  cudaGetSymbolAddress((void**)&alo,  g_alo);
    cudaGetSymbolAddress((void**)&s,    g_s);    cudaGetSymbolAddress((void**)&o,    g_o);

    const int SMEM_BYTES = 2 * 32768;
    cudaFuncSetAttribute(mma_gemm<0>, cudaFuncAttributeMaxDynamicSharedMemorySize, SMEM_BYTES);
    cudaFuncSetAttribute(mma_gemm<1>, cudaFuncAttributeMaxDynamicSharedMemorySize, SMEM_BYTES);

    // 1) LayerNorm -> xn split bf16 [B*NT, C]
    ln_kernel<<<dim3(NT / 32, NB), 256>>>(x, gamma, beta, xnhi, xnlo);

    // 2) weight transpose+split
    wsplitT_kernel<<<NC, NC>>>(Wq, wqhi, wqlo);
    wsplitT_kernel<<<NC, NC>>>(Wk, wkhi, wklo);
    wsplitT_kernel<<<NC, NC>>>(Wv, wvhi, wvlo);

    // 3) Q = xn @ Wq : A=[16384,256], B=WqT[256,256] -> split bf16
    mma_gemm<1><<<dim3(2, 128, 1), 256, SMEM_BYTES>>>(
        xnhi, xnlo, NC, 0, wqhi, wqlo, NC, 0,
        nullptr, qhi, qlo, NC, 0, NC);
    mma_gemm<1><<<dim3(2, 128, 1), 256, SMEM_BYTES>>>(
        xnhi, xnlo, NC, 0, wkhi, wklo, NC, 0,
        nullptr, khi, klo, NC, 0, NC);
    // V^T = WvT @ xn^T : A=WvT[256,256], B=xn[16384,256] -> vT split [256, B*NT]
    mma_gemm<1><<<dim3(128, 2, 1), 256, SMEM_BYTES>>>(
        wvhi, wvlo, NC, 0, xnhi, xnlo, NC, 0,
        nullptr, vThi, vTlo, (long)NB * NT, 0, NC);

    // 4) S = Q @ K^T per batch -> fp32 [4096,4096]
    mma_gemm<0><<<dim3(32, 32, NB), 256, SMEM_BYTES>>>(
        qhi, qlo, NC, (long)NT * NC, khi, klo, NC, (long)NT * NC,
        s, nullptr, nullptr, NT, (long)NT * NT, NC);

    // 5) attn = a1*softmax(S) + a2*relu(S)^2 -> split bf16
    mix_kernel<<<dim3(NT, NB), 256>>>(w1, w2, s, ahi, alo);

    // 6) O = attn @ V per batch : A=attn[4096,4096], B=vT[256, 4096 cols @ ld 16384]
    mma_gemm<0><<<dim3(2, 32, NB), 256, SMEM_BYTES>>>(
        ahi, alo, NT, (long)NT * NT, vThi, vTlo, (long)NB * NT, NT,
        o, nullptr, nullptr, NC, (long)NT * NC, NT);

    // 7) transpose + residual
    out_kernel<<<dim3(NT / 32, NC / 32, NB), dim3(32, 8)>>>(o, xnhi, xnlo, out);
}